// round 2
// baseline (speedup 1.0000x reference)
#include <cuda_runtime.h>
#include <math.h>

#define MB_   128   // batch m
#define IND_  1024  // in_dim
#define OUTD_ 1024  // out_dim
#define HD_   256   // h_dim
#define RD_   1025  // in_dim + 1

// ---------------- scratch (static device globals; no allocation) ----------------
__device__ float g_xT[IND_ * MB_];          // xT[k][m]
__device__ float g_hT[HD_ * MB_];           // hT[j][m]
__device__ float g_hpart[4 * HD_ * MB_];    // k-split partials for h
__device__ float g_Msq[RD_];                // sum_c M[r,c]^2
__device__ float g_aT[RD_ * MB_];           // (x_aug * mu)[r][m]
__device__ float g_bT[RD_ * MB_];           // (x_aug * sqrt(var_r))[r][m]
__device__ float g_vcT[OUTD_ * MB_];        // sqrt(var_c)[c][m]
__device__ float g_t1part[4 * MB_ * OUTD_]; // k-split partials of a@M
__device__ float g_svarr[129 * MB_];
__device__ float g_slvr [129 * MB_];
__device__ float g_smu2 [129 * MB_];
__device__ float g_svarc[128 * MB_];
__device__ float g_slvc [128 * MB_];

// ---------------- K0: transpose x + Msq ----------------
__global__ void k0_prep(const float* __restrict__ x, const float* __restrict__ Mmat) {
    int b = blockIdx.x;
    if (b < 128) {
        __shared__ float sm[32][33];
        int tk = b & 31, tm = b >> 5;             // k-tile 0..31, m-tile 0..3
        int tx = threadIdx.x & 31, ty = threadIdx.x >> 5;  // ty 0..7
        #pragma unroll
        for (int i = 0; i < 4; i++) {
            int row = tm * 32 + ty + i * 8;       // m
            int col = tk * 32 + tx;               // k
            sm[ty + i * 8][tx] = x[row * IND_ + col];
        }
        __syncthreads();
        #pragma unroll
        for (int i = 0; i < 4; i++) {
            int kk = tk * 32 + ty + i * 8;
            int mm = tm * 32 + tx;
            g_xT[kk * MB_ + mm] = sm[tx][ty + i * 8];
        }
    } else {
        int r = b - 128;                          // 0..1024
        float s = 0.f;
        for (int c = threadIdx.x; c < OUTD_; c += 256) {
            float v = Mmat[r * OUTD_ + c];
            s += v * v;
        }
        __shared__ float red[256];
        red[threadIdx.x] = s;
        __syncthreads();
        for (int off = 128; off > 0; off >>= 1) {
            if (threadIdx.x < off) red[threadIdx.x] += red[threadIdx.x + off];
            __syncthreads();
        }
        if (threadIdx.x == 0) g_Msq[r] = red[0];
    }
}

// ---------------- K1: h partial GEMM (k-split x4) ----------------
__global__ void k1_h(const float* __restrict__ Wxh) {
    int jb = blockIdx.x;           // 0..31 (8 j's each)
    int ks = blockIdx.y;           // 0..3
    int m  = threadIdx.x;          // 0..127
    int j0 = jb * 8;
    int kbeg = ks * 256;
    __shared__ __align__(16) float Ws[8][68];
    float acc[8];
    #pragma unroll
    for (int j = 0; j < 8; j++) acc[j] = 0.f;
    for (int kb = kbeg; kb < kbeg + 256; kb += 64) {
        int jj  = threadIdx.x >> 4;
        int kk4 = (threadIdx.x & 15) * 4;
        float4 w4 = *reinterpret_cast<const float4*>(&Wxh[(j0 + jj) * IND_ + kb + kk4]);
        *reinterpret_cast<float4*>(&Ws[jj][kk4]) = w4;
        __syncthreads();
        #pragma unroll 8
        for (int k = 0; k < 64; k++) {
            float hv = g_xT[(kb + k) * MB_ + m];
            #pragma unroll
            for (int j = 0; j < 8; j++) acc[j] += hv * Ws[j][k];
        }
        __syncthreads();
    }
    #pragma unroll
    for (int j = 0; j < 8; j++)
        g_hpart[ks * (HD_ * MB_) + (j0 + j) * MB_ + m] = acc[j];
}

// ---------------- K1b: combine + bias + relu ----------------
__global__ void k1b_combine(const float* __restrict__ bxh) {
    int idx = blockIdx.x * 256 + threadIdx.x;     // < 32768
    int j = idx >> 7;
    float s = g_hpart[idx] + g_hpart[32768 + idx] + g_hpart[65536 + idx] + g_hpart[98304 + idx]
            + bxh[j];
    g_hT[idx] = fmaxf(s, 0.f);
}

// ---------------- K2: three heads fused ----------------
__global__ void k2_heads(const float* __restrict__ Whmu,    const float* __restrict__ bhmu,
                         const float* __restrict__ Whlvin,  const float* __restrict__ bhlvin,
                         const float* __restrict__ Whlvout, const float* __restrict__ bhlvout) {
    __shared__ __align__(16) float W0s[8][68];
    __shared__ __align__(16) float W1s[8][68];
    int m   = threadIdx.x;         // 0..127
    int blk = blockIdx.x;          // 0..256
    bool famA = blk < 129;         // mu + logvar_r (r rows); else logvar_c (c cols)
    int r0 = famA ? blk * 8 : (blk - 129) * 8;
    const float* W0 = famA ? Whmu : Whlvout;
    const float* W1 = Whlvin;
    int rmax = famA ? RD_ : OUTD_;
    float a0[8], a1[8];
    #pragma unroll
    for (int j = 0; j < 8; j++) { a0[j] = 0.f; a1[j] = 0.f; }

    for (int kb = 0; kb < 256; kb += 64) {
        int jj  = threadIdx.x >> 4;
        int kk4 = (threadIdx.x & 15) * 4;
        int r = r0 + jj;
        float4 w0 = make_float4(0.f, 0.f, 0.f, 0.f), w1 = w0;
        if (r < rmax) {
            w0 = *reinterpret_cast<const float4*>(&W0[r * HD_ + kb + kk4]);
            if (famA) w1 = *reinterpret_cast<const float4*>(&W1[r * HD_ + kb + kk4]);
        }
        *reinterpret_cast<float4*>(&W0s[jj][kk4]) = w0;
        *reinterpret_cast<float4*>(&W1s[jj][kk4]) = w1;
        __syncthreads();
        if (famA) {
            #pragma unroll 4
            for (int k = 0; k < 64; k++) {
                float hv = g_hT[(kb + k) * MB_ + m];
                #pragma unroll
                for (int j = 0; j < 8; j++) { a0[j] += hv * W0s[j][k]; a1[j] += hv * W1s[j][k]; }
            }
        } else {
            #pragma unroll 4
            for (int k = 0; k < 64; k++) {
                float hv = g_hT[(kb + k) * MB_ + m];
                #pragma unroll
                for (int j = 0; j < 8; j++) a0[j] += hv * W0s[j][k];
            }
        }
        __syncthreads();
    }

    if (famA) {
        float svr = 0.f, slvr = 0.f, smu2 = 0.f;
        #pragma unroll
        for (int j = 0; j < 8; j++) {
            int r = r0 + j;
            if (r < RD_) {
                float mu = a0[j] + bhmu[r];
                float lv = a1[j] + bhlvin[r];
                float xa = (r < IND_) ? g_xT[r * MB_ + m] : 1.f;
                g_aT[r * MB_ + m] = xa * mu;
                float vr = expf(lv);
                g_bT[r * MB_ + m] = xa * sqrtf(vr);
                svr += vr; slvr += lv; smu2 += mu * mu * g_Msq[r];
            }
        }
        g_svarr[blk * MB_ + m] = svr;
        g_slvr [blk * MB_ + m] = slvr;
        g_smu2 [blk * MB_ + m] = smu2;
    } else {
        int cb = blk - 129;
        float svc = 0.f, slvc = 0.f;
        #pragma unroll
        for (int j = 0; j < 8; j++) {
            int c = r0 + j;
            float lv = a0[j] + bhlvout[c];
            float vc = expf(lv);
            g_vcT[c * MB_ + m] = sqrtf(vc);
            svc += vc; slvc += lv;
        }
        g_svarc[cb * MB_ + m] = svc;
        g_slvc [cb * MB_ + m] = slvc;
    }
}

// ---------------- K3: term1 = a @ M (k-split x4, tiled) ----------------
__global__ void k3_term1(const float* __restrict__ Mmat) {
    int cb = blockIdx.x;           // 0..15 -> c0 = cb*64
    int mb = blockIdx.y;           // 0..3  -> m0 = mb*32
    int ks = blockIdx.z;           // 0..3
    int c0 = cb * 64, m0 = mb * 32;
    int rbeg = ks * 257;
    int rcnt = min(257, RD_ - rbeg);
    __shared__ __align__(16) float As[32][32];
    __shared__ __align__(16) float Bs[32][64];
    int t = threadIdx.x;
    int lane = t & 31, w = t >> 5;
    float acc[8];
    #pragma unroll
    for (int j = 0; j < 8; j++) acc[j] = 0.f;

    for (int ch = 0; ch < 9; ch++) {
        #pragma unroll
        for (int i = 0; i < 4; i++) {
            int idx = t + i * 256;
            int kk = idx >> 5, mm = idx & 31;
            int roff = ch * 32 + kk;
            As[kk][mm] = (roff < rcnt) ? g_aT[(rbeg + roff) * MB_ + m0 + mm] : 0.f;
        }
        #pragma unroll
        for (int i = 0; i < 8; i++) {
            int idx = t + i * 256;
            int kk = idx >> 6, cc = idx & 63;
            int roff = ch * 32 + kk;
            Bs[kk][cc] = (roff < rcnt) ? Mmat[(rbeg + roff) * OUTD_ + c0 + cc] : 0.f;
        }
        __syncthreads();
        #pragma unroll 8
        for (int kk = 0; kk < 32; kk++) {
            float av = As[kk][lane];
            float4 b0 = *reinterpret_cast<const float4*>(&Bs[kk][w * 8]);
            float4 b1 = *reinterpret_cast<const float4*>(&Bs[kk][w * 8 + 4]);
            acc[0] += av * b0.x; acc[1] += av * b0.y; acc[2] += av * b0.z; acc[3] += av * b0.w;
            acc[4] += av * b1.x; acc[5] += av * b1.y; acc[6] += av * b1.z; acc[7] += av * b1.w;
        }
        __syncthreads();
    }
    float* dst = &g_t1part[ks * (MB_ * OUTD_) + (m0 + lane) * OUTD_ + c0 + w * 8];
    *reinterpret_cast<float4*>(dst)     = make_float4(acc[0], acc[1], acc[2], acc[3]);
    *reinterpret_cast<float4*>(dst + 4) = make_float4(acc[4], acc[5], acc[6], acc[7]);
}

// ---------------- K4: main E-streaming kernel (unroll-16 rows for MLP) ----------------
__global__ void k4_main(const float* __restrict__ E, float* __restrict__ out) {
    int cb = blockIdx.x;           // 0..1
    int m  = blockIdx.y;           // 0..127
    int c0 = cb * 512 + threadIdx.x * 4;
    const float* Em   = E + (size_t)m * (RD_ * OUTD_);
    const float* bcol = g_bT + m;
    float4 acc = make_float4(0.f, 0.f, 0.f, 0.f);
    for (int r = 0; r < 1024; r += 16) {
        float4 e[16];
        float  bv[16];
        #pragma unroll
        for (int i = 0; i < 16; i++) {
            bv[i] = bcol[(r + i) * MB_];
            e[i]  = __ldcs(reinterpret_cast<const float4*>(Em + (size_t)(r + i) * OUTD_ + c0));
        }
        #pragma unroll
        for (int i = 0; i < 16; i++) {
            acc.x += bv[i] * e[i].x; acc.y += bv[i] * e[i].y;
            acc.z += bv[i] * e[i].z; acc.w += bv[i] * e[i].w;
        }
    }
    {   // r = 1024 (bias row)
        float  bv = bcol[1024 * MB_];
        float4 e  = __ldcs(reinterpret_cast<const float4*>(Em + (size_t)1024 * OUTD_ + c0));
        acc.x += bv * e.x; acc.y += bv * e.y; acc.z += bv * e.z; acc.w += bv * e.w;
    }
    int oidx = m * OUTD_ + c0;
    float4 t1 = make_float4(0.f, 0.f, 0.f, 0.f);
    #pragma unroll
    for (int ks = 0; ks < 4; ks++) {
        float4 p = *reinterpret_cast<const float4*>(&g_t1part[ks * (MB_ * OUTD_) + oidx]);
        t1.x += p.x; t1.y += p.y; t1.z += p.z; t1.w += p.w;
    }
    float4 vc;
    vc.x = g_vcT[(c0 + 0) * MB_ + m];
    vc.y = g_vcT[(c0 + 1) * MB_ + m];
    vc.z = g_vcT[(c0 + 2) * MB_ + m];
    vc.w = g_vcT[(c0 + 3) * MB_ + m];
    float4 o;
    o.x = t1.x + vc.x * acc.x;
    o.y = t1.y + vc.y * acc.y;
    o.z = t1.z + vc.z * acc.z;
    o.w = t1.w + vc.w * acc.w;
    *reinterpret_cast<float4*>(&out[oidx]) = o;
}

// ---------------- K5: D_KL final reduction (double) ----------------
__global__ void k5_dkl(float* __restrict__ dkl_out) {
    int m = threadIdx.x;           // 0..127
    double svr = 0.0, slvr = 0.0, smu2 = 0.0, svc = 0.0, slvc = 0.0;
    for (int b = 0; b < 129; b++) {
        svr  += (double)g_svarr[b * MB_ + m];
        slvr += (double)g_slvr [b * MB_ + m];
        smu2 += (double)g_smu2 [b * MB_ + m];
    }
    for (int b = 0; b < 128; b++) {
        svc  += (double)g_svarc[b * MB_ + m];
        slvc += (double)g_slvc [b * MB_ + m];
    }
    double dm = 0.5 * (svr * svc + smu2 - (double)RD_ * (double)OUTD_
                       - (double)OUTD_ * slvr - (double)RD_ * slvc);
    __shared__ double red[128];
    red[m] = dm;
    __syncthreads();
    for (int off = 64; off > 0; off >>= 1) {
        if (m < off) red[m] += red[m + off];
        __syncthreads();
    }
    if (m == 0) *dkl_out = (float)(red[0] / (double)MB_);
}

// ---------------- launcher ----------------
extern "C" void kernel_launch(void* const* d_in, const int* in_sizes, int n_in,
                              void* d_out, int out_size) {
    const float* x        = (const float*)d_in[0];
    const float* E        = (const float*)d_in[1];
    const float* Mmat     = (const float*)d_in[2];
    const float* Wxh      = (const float*)d_in[3];
    const float* bxh      = (const float*)d_in[4];
    const float* Whmu     = (const float*)d_in[5];
    const float* bhmu     = (const float*)d_in[6];
    const float* Whlvin   = (const float*)d_in[7];
    const float* bhlvin   = (const float*)d_in[8];
    const float* Whlvout  = (const float*)d_in[9];
    const float* bhlvout  = (const float*)d_in[10];
    float* out = (float*)d_out;

    k0_prep    <<<1153, 256>>>(x, Mmat);
    k1_h       <<<dim3(32, 4), 128>>>(Wxh);
    k1b_combine<<<128, 256>>>(bxh);
    k2_heads   <<<257, 128>>>(Whmu, bhmu, Whlvin, bhlvin, Whlvout, bhlvout);
    k3_term1   <<<dim3(16, 4, 4), 256>>>(Mmat);
    k4_main    <<<dim3(2, 128), 128>>>(E, out);
    k5_dkl     <<<1, 128>>>(out + (out_size - 1));
}

// round 4
// speedup vs baseline: 2.0884x; 2.0884x over previous
#include <cuda_runtime.h>
#include <math.h>

#define MB_   128   // batch m
#define IND_  1024  // in_dim
#define OUTD_ 1024  // out_dim
#define HD_   256   // h_dim
#define RD_   1025  // in_dim + 1

// ---------------- scratch (static device globals; no allocation) ----------------
__device__ float g_xT[IND_ * MB_];          // xT[k][m]
__device__ float g_hT[HD_ * MB_];           // hT[j][m]
__device__ float g_hpart[4 * HD_ * MB_];    // k-split partials for h
__device__ float g_Msq[RD_];                // sum_c M[r,c]^2
__device__ float g_aT[RD_ * MB_];           // (x_aug * mu)[r][m]
__device__ float g_bT[RD_ * MB_];           // (x_aug * sqrt(var_r))[r][m]
__device__ float g_vcT[OUTD_ * MB_];        // sqrt(var_c)[c][m]
__device__ float g_t1part[4 * MB_ * OUTD_]; // k-split partials of a@M
__device__ float g_svarr[129 * MB_];
__device__ float g_slvr [129 * MB_];
__device__ float g_smu2 [129 * MB_];
__device__ float g_svarc[128 * MB_];
__device__ float g_slvc [128 * MB_];

// ---------------- K0: transpose x + Msq ----------------
__global__ void k0_prep(const float* __restrict__ x, const float* __restrict__ Mmat) {
    int b = blockIdx.x;
    if (b < 128) {
        __shared__ float sm[32][33];
        int tk = b & 31, tm = b >> 5;
        int tx = threadIdx.x & 31, ty = threadIdx.x >> 5;
        #pragma unroll
        for (int i = 0; i < 4; i++) {
            int row = tm * 32 + ty + i * 8;
            int col = tk * 32 + tx;
            sm[ty + i * 8][tx] = x[row * IND_ + col];
        }
        __syncthreads();
        #pragma unroll
        for (int i = 0; i < 4; i++) {
            int kk = tk * 32 + ty + i * 8;
            int mm = tm * 32 + tx;
            g_xT[kk * MB_ + mm] = sm[tx][ty + i * 8];
        }
    } else {
        int r = b - 128;
        float s = 0.f;
        for (int c = threadIdx.x; c < OUTD_; c += 256) {
            float v = Mmat[r * OUTD_ + c];
            s += v * v;
        }
        __shared__ float red[256];
        red[threadIdx.x] = s;
        __syncthreads();
        for (int off = 128; off > 0; off >>= 1) {
            if (threadIdx.x < off) red[threadIdx.x] += red[threadIdx.x + off];
            __syncthreads();
        }
        if (threadIdx.x == 0) g_Msq[r] = red[0];
    }
}

// ---------------- K1: h partial GEMM (k-split x4 grid, x2 in-block) ----------------
__global__ void k1_h(const float* __restrict__ Wxh) {
    int jb = blockIdx.x;            // 0..31 (8 j's each)
    int ks = blockIdx.y;            // 0..3
    int tid = threadIdx.x;          // 0..255
    int m = tid & 127;
    int g = tid >> 7;               // 0..1, in-block k-split
    int j0 = jb * 8;
    int kbeg = ks * 256 + g * 128;
    __shared__ __align__(16) float Ws[2][8][68];
    __shared__ float red[8][128];
    float acc[8];
    #pragma unroll
    for (int j = 0; j < 8; j++) acc[j] = 0.f;
    for (int kb = kbeg; kb < kbeg + 128; kb += 64) {
        int jj  = m >> 4;
        int kk4 = (m & 15) * 4;
        float4 w4 = *reinterpret_cast<const float4*>(&Wxh[(j0 + jj) * IND_ + kb + kk4]);
        *reinterpret_cast<float4*>(&Ws[g][jj][kk4]) = w4;
        __syncthreads();
        #pragma unroll 8
        for (int k = 0; k < 64; k++) {
            float hv = g_xT[(kb + k) * MB_ + m];
            #pragma unroll
            for (int j = 0; j < 8; j++) acc[j] += hv * Ws[g][j][k];
        }
        __syncthreads();
    }
    if (g == 1) {
        #pragma unroll
        for (int j = 0; j < 8; j++) red[j][m] = acc[j];
    }
    __syncthreads();
    if (g == 0) {
        #pragma unroll
        for (int j = 0; j < 8; j++)
            g_hpart[ks * (HD_ * MB_) + (j0 + j) * MB_ + m] = acc[j] + red[j][m];
    }
}

// ---------------- K1b: combine + bias + relu ----------------
__global__ void k1b_combine(const float* __restrict__ bxh) {
    int idx = blockIdx.x * 256 + threadIdx.x;     // < 32768
    int j = idx >> 7;
    float s = g_hpart[idx] + g_hpart[32768 + idx] + g_hpart[65536 + idx] + g_hpart[98304 + idx]
            + bxh[j];
    g_hT[idx] = fmaxf(s, 0.f);
}

// ---------------- K2: three heads fused (256 thr, 2-way in-block k-split) ----------------
__global__ void k2_heads(const float* __restrict__ Whmu,    const float* __restrict__ bhmu,
                         const float* __restrict__ Whlvin,  const float* __restrict__ bhlvin,
                         const float* __restrict__ Whlvout, const float* __restrict__ bhlvout) {
    __shared__ __align__(16) float W0s[2][8][68];
    __shared__ __align__(16) float W1s[2][8][68];
    __shared__ float red0[8][128];
    __shared__ float red1[8][128];
    int tid = threadIdx.x;
    int m = tid & 127;
    int g = tid >> 7;              // 0..1
    int blk = blockIdx.x;          // 0..256
    bool famA = blk < 129;
    int r0 = famA ? blk * 8 : (blk - 129) * 8;
    const float* W0 = famA ? Whmu : Whlvout;
    const float* W1 = Whlvin;
    int rmax = famA ? RD_ : OUTD_;
    float a0[8], a1[8];
    #pragma unroll
    for (int j = 0; j < 8; j++) { a0[j] = 0.f; a1[j] = 0.f; }

    int kbeg = g * 128;
    for (int kb = kbeg; kb < kbeg + 128; kb += 64) {
        int jj  = m >> 4;
        int kk4 = (m & 15) * 4;
        int r = r0 + jj;
        float4 w0 = make_float4(0.f, 0.f, 0.f, 0.f), w1 = w0;
        if (r < rmax) {
            w0 = *reinterpret_cast<const float4*>(&W0[r * HD_ + kb + kk4]);
            if (famA) w1 = *reinterpret_cast<const float4*>(&W1[r * HD_ + kb + kk4]);
        }
        *reinterpret_cast<float4*>(&W0s[g][jj][kk4]) = w0;
        *reinterpret_cast<float4*>(&W1s[g][jj][kk4]) = w1;
        __syncthreads();
        if (famA) {
            #pragma unroll 4
            for (int k = 0; k < 64; k++) {
                float hv = g_hT[(kb + k) * MB_ + m];
                #pragma unroll
                for (int j = 0; j < 8; j++) { a0[j] += hv * W0s[g][j][k]; a1[j] += hv * W1s[g][j][k]; }
            }
        } else {
            #pragma unroll 4
            for (int k = 0; k < 64; k++) {
                float hv = g_hT[(kb + k) * MB_ + m];
                #pragma unroll
                for (int j = 0; j < 8; j++) a0[j] += hv * W0s[g][j][k];
            }
        }
        __syncthreads();
    }

    if (g == 1) {
        #pragma unroll
        for (int j = 0; j < 8; j++) { red0[j][m] = a0[j]; red1[j][m] = a1[j]; }
    }
    __syncthreads();
    if (g != 0) return;
    #pragma unroll
    for (int j = 0; j < 8; j++) { a0[j] += red0[j][m]; a1[j] += red1[j][m]; }

    if (famA) {
        float svr = 0.f, slvr = 0.f, smu2 = 0.f;
        #pragma unroll
        for (int j = 0; j < 8; j++) {
            int r = r0 + j;
            if (r < RD_) {
                float mu = a0[j] + bhmu[r];
                float lv = a1[j] + bhlvin[r];
                float xa = (r < IND_) ? g_xT[r * MB_ + m] : 1.f;
                g_aT[r * MB_ + m] = xa * mu;
                float vr = expf(lv);
                g_bT[r * MB_ + m] = xa * sqrtf(vr);
                svr += vr; slvr += lv; smu2 += mu * mu * g_Msq[r];
            }
        }
        g_svarr[blk * MB_ + m] = svr;
        g_slvr [blk * MB_ + m] = slvr;
        g_smu2 [blk * MB_ + m] = smu2;
    } else {
        int cb = blk - 129;
        float svc = 0.f, slvc = 0.f;
        #pragma unroll
        for (int j = 0; j < 8; j++) {
            int c = r0 + j;
            float lv = a0[j] + bhlvout[c];
            float vc = expf(lv);
            g_vcT[c * MB_ + m] = sqrtf(vc);
            svc += vc; slvc += lv;
        }
        g_svarc[cb * MB_ + m] = svc;
        g_slvc [cb * MB_ + m] = slvc;
    }
}

// ---------------- K3: term1 = a @ M (k-split x4, tiled) ----------------
__global__ void k3_term1(const float* __restrict__ Mmat) {
    int cb = blockIdx.x;           // 0..15
    int mb = blockIdx.y;           // 0..3
    int ks = blockIdx.z;           // 0..3
    int c0 = cb * 64, m0 = mb * 32;
    int rbeg = ks * 257;
    int rcnt = min(257, RD_ - rbeg);
    __shared__ __align__(16) float As[32][32];
    __shared__ __align__(16) float Bs[32][64];
    int t = threadIdx.x;
    int lane = t & 31, w = t >> 5;
    float acc[8];
    #pragma unroll
    for (int j = 0; j < 8; j++) acc[j] = 0.f;

    for (int ch = 0; ch < 9; ch++) {
        #pragma unroll
        for (int i = 0; i < 4; i++) {
            int idx = t + i * 256;
            int kk = idx >> 5, mm = idx & 31;
            int roff = ch * 32 + kk;
            As[kk][mm] = (roff < rcnt) ? g_aT[(rbeg + roff) * MB_ + m0 + mm] : 0.f;
        }
        #pragma unroll
        for (int i = 0; i < 8; i++) {
            int idx = t + i * 256;
            int kk = idx >> 6, cc = idx & 63;
            int roff = ch * 32 + kk;
            Bs[kk][cc] = (roff < rcnt) ? Mmat[(rbeg + roff) * OUTD_ + c0 + cc] : 0.f;
        }
        __syncthreads();
        #pragma unroll 8
        for (int kk = 0; kk < 32; kk++) {
            float av = As[kk][lane];
            float4 b0 = *reinterpret_cast<const float4*>(&Bs[kk][w * 8]);
            float4 b1 = *reinterpret_cast<const float4*>(&Bs[kk][w * 8 + 4]);
            acc[0] += av * b0.x; acc[1] += av * b0.y; acc[2] += av * b0.z; acc[3] += av * b0.w;
            acc[4] += av * b1.x; acc[5] += av * b1.y; acc[6] += av * b1.z; acc[7] += av * b1.w;
        }
        __syncthreads();
    }
    float* dst = &g_t1part[ks * (MB_ * OUTD_) + (m0 + lane) * OUTD_ + c0 + w * 8];
    *reinterpret_cast<float4*>(dst)     = make_float4(acc[0], acc[1], acc[2], acc[3]);
    *reinterpret_cast<float4*>(dst + 4) = make_float4(acc[4], acc[5], acc[6], acc[7]);
}

// ---------------- K4: main E-streaming kernel (512 thr, 4-way r-split) ----------------
__global__ void __launch_bounds__(512, 2) k4_main(const float* __restrict__ E, float* __restrict__ out) {
    int cb = blockIdx.x;            // 0..1
    int m  = blockIdx.y;            // 0..127
    int tid = threadIdx.x;
    int lane = tid & 127;
    int g = tid >> 7;               // 0..3, r-slice
    int c0 = cb * 512 + lane * 4;
    const float* Em   = E + (size_t)m * (RD_ * OUTD_);
    const float* bcol = g_bT + m;
    float4 acc = make_float4(0.f, 0.f, 0.f, 0.f);
    int rbeg = g * 256;
    for (int r = rbeg; r < rbeg + 256; r += 8) {
        float4 e[8];
        float  bv[8];
        #pragma unroll
        for (int i = 0; i < 8; i++) {
            bv[i] = bcol[(r + i) * MB_];
            e[i]  = __ldcs(reinterpret_cast<const float4*>(Em + (size_t)(r + i) * OUTD_ + c0));
        }
        #pragma unroll
        for (int i = 0; i < 8; i++) {
            acc.x += bv[i] * e[i].x; acc.y += bv[i] * e[i].y;
            acc.z += bv[i] * e[i].z; acc.w += bv[i] * e[i].w;
        }
    }
    if (g == 3) {   // r = 1024 (bias row)
        float  bv = bcol[1024 * MB_];
        float4 e  = __ldcs(reinterpret_cast<const float4*>(Em + (size_t)1024 * OUTD_ + c0));
        acc.x += bv * e.x; acc.y += bv * e.y; acc.z += bv * e.z; acc.w += bv * e.w;
    }
    __shared__ __align__(16) float4 sred[512];
    sred[tid] = acc;
    __syncthreads();
    if (tid >= 128) return;
    float4 a0 = sred[tid];
    float4 a1 = sred[tid + 128];
    float4 a2 = sred[tid + 256];
    float4 a3 = sred[tid + 384];
    acc.x = (a0.x + a1.x) + (a2.x + a3.x);
    acc.y = (a0.y + a1.y) + (a2.y + a3.y);
    acc.z = (a0.z + a1.z) + (a2.z + a3.z);
    acc.w = (a0.w + a1.w) + (a2.w + a3.w);

    int oidx = m * OUTD_ + c0;
    float4 t1 = make_float4(0.f, 0.f, 0.f, 0.f);
    #pragma unroll
    for (int ks = 0; ks < 4; ks++) {
        float4 p = *reinterpret_cast<const float4*>(&g_t1part[ks * (MB_ * OUTD_) + oidx]);
        t1.x += p.x; t1.y += p.y; t1.z += p.z; t1.w += p.w;
    }
    float4 vc;
    vc.x = g_vcT[(c0 + 0) * MB_ + m];
    vc.y = g_vcT[(c0 + 1) * MB_ + m];
    vc.z = g_vcT[(c0 + 2) * MB_ + m];
    vc.w = g_vcT[(c0 + 3) * MB_ + m];
    float4 o;
    o.x = t1.x + vc.x * acc.x;
    o.y = t1.y + vc.y * acc.y;
    o.z = t1.z + vc.z * acc.z;
    o.w = t1.w + vc.w * acc.w;
    *reinterpret_cast<float4*>(&out[oidx]) = o;
}

// ---------------- K5: D_KL final reduction (double) ----------------
__global__ void k5_dkl(float* __restrict__ dkl_out) {
    int m = threadIdx.x;
    double svr = 0.0, slvr = 0.0, smu2 = 0.0, svc = 0.0, slvc = 0.0;
    for (int b = 0; b < 129; b++) {
        svr  += (double)g_svarr[b * MB_ + m];
        slvr += (double)g_slvr [b * MB_ + m];
        smu2 += (double)g_smu2 [b * MB_ + m];
    }
    for (int b = 0; b < 128; b++) {
        svc  += (double)g_svarc[b * MB_ + m];
        slvc += (double)g_slvc [b * MB_ + m];
    }
    double dm = 0.5 * (svr * svc + smu2 - (double)RD_ * (double)OUTD_
                       - (double)OUTD_ * slvr - (double)RD_ * slvc);
    __shared__ double red[128];
    red[m] = dm;
    __syncthreads();
    for (int off = 64; off > 0; off >>= 1) {
        if (m < off) red[m] += red[m + off];
        __syncthreads();
    }
    if (m == 0) *dkl_out = (float)(red[0] / (double)MB_);
}

// ---------------- launcher ----------------
extern "C" void kernel_launch(void* const* d_in, const int* in_sizes, int n_in,
                              void* d_out, int out_size) {
    const float* x        = (const float*)d_in[0];
    const float* E        = (const float*)d_in[1];
    const float* Mmat     = (const float*)d_in[2];
    const float* Wxh      = (const float*)d_in[3];
    const float* bxh      = (const float*)d_in[4];
    const float* Whmu     = (const float*)d_in[5];
    const float* bhmu     = (const float*)d_in[6];
    const float* Whlvin   = (const float*)d_in[7];
    const float* bhlvin   = (const float*)d_in[8];
    const float* Whlvout  = (const float*)d_in[9];
    const float* bhlvout  = (const float*)d_in[10];
    float* out = (float*)d_out;

    k0_prep    <<<1153, 256>>>(x, Mmat);
    k1_h       <<<dim3(32, 4), 256>>>(Wxh);
    k1b_combine<<<128, 256>>>(bxh);
    k2_heads   <<<257, 256>>>(Whmu, bhmu, Whlvin, bhlvin, Whlvout, bhlvout);
    k3_term1   <<<dim3(16, 4, 4), 256>>>(Mmat);
    k4_main    <<<dim3(2, 128), 512>>>(E, out);
    k5_dkl     <<<1, 128>>>(out + (out_size - 1));
}